// round 3
// baseline (speedup 1.0000x reference)
#include <cuda_runtime.h>

#define N_NODES 50000
#define N_GRAPHS 128
#define HID 512
#define NWALK 12
#define QELEMS (N_GRAPHS * HID)

// ---------------- device scratch (no allocations allowed) ----------------
__device__ int   g_pb[N_NODES];
__device__ int   g_counts[N_GRAPHS];
__device__ int   g_cursors[N_GRAPHS];
__device__ int   g_offsets[N_GRAPHS + 1];
__device__ int   g_order[N_NODES];
__device__ float g_Q[QELEMS];
__device__ float g_R0[QELEMS];
__device__ float g_R1[QELEMS];
__device__ float g_R2[QELEMS];
__device__ float g_P0[QELEMS];
__device__ float g_P1[QELEMS];

// ---------------- zero everything that accumulates ----------------
__global__ void k_init() {
    int i = blockIdx.x * blockDim.x + threadIdx.x;
    if (i < N_GRAPHS) { g_counts[i] = 0; g_cursors[i] = 0; }
    if (i < QELEMS) {
        g_Q[i]  = 0.f;
        g_R0[i] = 0.f;
        g_R1[i] = 0.f;
        g_R2[i] = 0.f;
    }
}

// ---------------- path_batch + histogram ----------------
__global__ void k_pb(const int* __restrict__ walk2, const int* __restrict__ batch) {
    int n = blockIdx.x * blockDim.x + threadIdx.x;
    if (n < N_NODES) {
        int g = batch[walk2[n]];   // walk2 row 0
        g_pb[n] = g;
        atomicAdd(&g_counts[g], 1);
    }
}

// ---------------- exclusive scan over 128 counts (trivial) ----------------
__global__ void k_scan() {
    if (threadIdx.x == 0 && blockIdx.x == 0) {
        int acc = 0;
        for (int g = 0; g < N_GRAPHS; g++) { g_offsets[g] = acc; acc += g_counts[g]; }
        g_offsets[N_GRAPHS] = acc;
    }
}

// ---------------- counting-sort scatter: nodes grouped by graph ----------------
__global__ void k_scatter() {
    int n = blockIdx.x * blockDim.x + threadIdx.x;
    if (n < N_NODES) {
        int g = g_pb[n];
        int pos = atomicAdd(&g_cursors[g], 1);
        g_order[g_offsets[g] + pos] = n;
    }
}

// ---------------- Q = A @ x  (the only big gather) ----------------
// grid (N_GRAPHS, 4 entry-slices), 128 threads; each thread owns 4 cols (float4).
__global__ __launch_bounds__(128)
void k_gather(const float* __restrict__ x,
              const int* __restrict__ w2,
              const int* __restrict__ w3,
              const int* __restrict__ w4) {
    int g = blockIdx.x;
    int slice = blockIdx.y;
    int start = g_offsets[g];
    int len   = g_offsets[g + 1] - start;
    int s0 = start + (len * slice)     / 4;
    int s1 = start + (len * (slice+1)) / 4;

    const float4* __restrict__ x4 = (const float4*)x;
    int c = threadIdx.x;                 // float4 column index 0..127
    float4 acc = make_float4(0.f, 0.f, 0.f, 0.f);

    for (int idx = s0; idx < s1; ++idx) {
        int n = g_order[idx];
        int j[NWALK];
        j[0]  = w2[n];
        j[1]  = w2[N_NODES + n];
        j[2]  = w2[2 * N_NODES + n];
        j[3]  = w3[n];
        j[4]  = w3[N_NODES + n];
        j[5]  = w3[2 * N_NODES + n];
        j[6]  = w3[3 * N_NODES + n];
        j[7]  = w4[n];
        j[8]  = w4[N_NODES + n];
        j[9]  = w4[2 * N_NODES + n];
        j[10] = w4[3 * N_NODES + n];
        j[11] = w4[4 * N_NODES + n];

        float4 v[NWALK];
        #pragma unroll
        for (int r = 0; r < NWALK; r++)
            v[r] = x4[j[r] * 128 + c];   // 12 independent L2 gathers in flight
        #pragma unroll
        for (int r = 0; r < NWALK; r++) {
            acc.x += v[r].x; acc.y += v[r].y; acc.z += v[r].z; acc.w += v[r].w;
        }
    }

    float* Qrow = &g_Q[g * HID + 4 * c];
    atomicAdd(Qrow + 0, acc.x);
    atomicAdd(Qrow + 1, acc.y);
    atomicAdd(Qrow + 2, acc.z);
    atomicAdd(Qrow + 3, acc.w);
}

// ---------------- small GEMM: R += A[128,512] @ W[512,512], split-K ----------------
// grid (8 col-tiles of 64, 16 K-slices of 32), 256 threads.
#define GK 32
#define GN 64
__global__ __launch_bounds__(256)
void k_gemm(const float* __restrict__ A, const float* __restrict__ W,
            float* __restrict__ R) {
    __shared__ float sA[GK][129];   // transposed A slice: sA[k][m], pad kills conflicts
    __shared__ float sB[GK][GN];
    int nb = blockIdx.x;            // col tile
    int kb = blockIdx.y;            // K slice
    int tid = threadIdx.x;

    for (int i = tid; i < 128 * GK; i += 256) {
        int m = i >> 5;             // i / GK
        int k = i & 31;
        sA[k][m] = A[m * HID + kb * GK + k];   // coalesced global read
    }
    for (int i = tid; i < GK * GN; i += 256) {
        int k = i >> 6;
        int cc = i & 63;
        sB[k][cc] = W[(kb * GK + k) * HID + nb * GN + cc];
    }
    __syncthreads();

    int trow = tid >> 4;            // 0..15 -> rows trow*8..+7
    int tcol = tid & 15;            // cols tcol*4..+3
    float acc[8][4];
    #pragma unroll
    for (int i = 0; i < 8; i++)
        #pragma unroll
        for (int jj = 0; jj < 4; jj++) acc[i][jj] = 0.f;

    #pragma unroll
    for (int k = 0; k < GK; k++) {
        float a[8], b[4];
        #pragma unroll
        for (int i = 0; i < 8; i++) a[i] = sA[k][trow * 8 + i];
        #pragma unroll
        for (int jj = 0; jj < 4; jj++) b[jj] = sB[k][tcol * 4 + jj];
        #pragma unroll
        for (int i = 0; i < 8; i++)
            #pragma unroll
            for (int jj = 0; jj < 4; jj++) acc[i][jj] += a[i] * b[jj];
    }

    #pragma unroll
    for (int i = 0; i < 8; i++)
        #pragma unroll
        for (int jj = 0; jj < 4; jj++)
            atomicAdd(&R[(trow * 8 + i) * HID + nb * GN + tcol * 4 + jj], acc[i][jj]);
}

// ---------------- epilogue: P = R + s*b ; out_slice = P / denom ----------------
__global__ void k_epi(const float* __restrict__ R, const float* __restrict__ bias,
                      float* __restrict__ Pout, float* __restrict__ out, int layer) {
    int i = blockIdx.x * blockDim.x + threadIdx.x;
    if (i < QELEMS) {
        int m = i >> 9;
        int c = i & 511;
        float cnt = (float)g_counts[m];
        float v = R[i] + 12.0f * cnt * bias[c];
        if (Pout) Pout[i] = v;
        out[m * (3 * HID) + layer * HID + c] = v / fmaxf(cnt, 1.0f);
    }
}

// ---------------- launch ----------------
extern "C" void kernel_launch(void* const* d_in, const int* in_sizes, int n_in,
                              void* d_out, int out_size) {
    const float* x     = (const float*)d_in[0];
    const int*   walk2 = (const int*)  d_in[1];
    const int*   walk3 = (const int*)  d_in[2];
    const int*   walk4 = (const int*)  d_in[3];
    const int*   batch = (const int*)  d_in[4];
    const float* W0 = (const float*)d_in[5];
    const float* b0 = (const float*)d_in[6];
    const float* W1 = (const float*)d_in[7];
    const float* b1 = (const float*)d_in[8];
    const float* W2 = (const float*)d_in[9];
    const float* b2 = (const float*)d_in[10];
    float* out = (float*)d_out;

    float *pQ, *pR0, *pR1, *pR2, *pP0, *pP1;
    cudaGetSymbolAddress((void**)&pQ,  g_Q);
    cudaGetSymbolAddress((void**)&pR0, g_R0);
    cudaGetSymbolAddress((void**)&pR1, g_R1);
    cudaGetSymbolAddress((void**)&pR2, g_R2);
    cudaGetSymbolAddress((void**)&pP0, g_P0);
    cudaGetSymbolAddress((void**)&pP1, g_P1);

    k_init<<<(QELEMS + 255) / 256, 256>>>();
    k_pb<<<(N_NODES + 255) / 256, 256>>>(walk2, batch);
    k_scan<<<1, 32>>>();
    k_scatter<<<(N_NODES + 255) / 256, 256>>>();
    k_gather<<<dim3(N_GRAPHS, 4), 128>>>(x, walk2, walk3, walk4);

    k_gemm<<<dim3(8, 16), 256>>>(pQ, W0, pR0);
    k_epi<<<(QELEMS + 255) / 256, 256>>>(pR0, b0, pP0, out, 0);

    k_gemm<<<dim3(8, 16), 256>>>(pP0, W1, pR1);
    k_epi<<<(QELEMS + 255) / 256, 256>>>(pR1, b1, pP1, out, 1);

    k_gemm<<<dim3(8, 16), 256>>>(pP1, W2, pR2);
    k_epi<<<(QELEMS + 255) / 256, 256>>>(pR2, b2, nullptr, out, 2);
}